// round 1
// baseline (speedup 1.0000x reference)
#include <cuda_runtime.h>
#include <math.h>

#define NB 8192
#define NP 64
#define NK 8
#define ND 512
#define NL 4
#define LN_EPS 1e-5f

__constant__ int c_C[NL]     = {256, 512, 1024, 2048};
__constant__ int c_wgoff[NL] = {0, 256, 768, 1792};   // row offsets into g_Wg

// ---- scratch (static device globals; allocation-free per rules) ----
__device__ float g_pm[NL * 2048];          // proto mean per level (padded to 2048)
__device__ float g_spqp[NL * 2];           // sum / sumsq of proto-mean part
__device__ float g_u[NL * ND];
__device__ float g_v[NL * ND];
__device__ float g_w[NL * ND];
__device__ float g_text[NK * ND];          // l2-normalized * clip(scale)/sqrt(D)
__device__ float g_Wg[3840 * ND];          // g_top ⊙ W_top, all levels stacked
__device__ float g_rs[NL * NB * 2];        // per-row (S, Q) of pooled
__device__ float g_h[(size_t)NL * NB * ND];// relu(LN(fused)@W + b), 64MB

struct PtrSet {
    const float* pooled[NL];
    const float* proto[NL];
    const float* lng[NL];
    const float* lnb[NL];
    const float* W[NL];
    const float* blin[NL];
    const float* text;
    const float* scale;
};

// ---- K1: proto column means + their sum/sumsq ----
__global__ void k_protomean(PtrSet ps) {
    int lvl = blockIdx.x;
    int C = c_C[lvl];
    const float* __restrict__ proto = ps.proto[lvl];
    float* pm = g_pm + lvl * 2048;
    float sS = 0.f, sQ = 0.f;
    for (int j = threadIdx.x; j < C; j += blockDim.x) {
        float s = 0.f;
        #pragma unroll 8
        for (int p = 0; p < NP; ++p) s += proto[p * C + j];
        float m = s * (1.0f / NP);
        pm[j] = m;
        sS += m;
        sQ += m * m;
    }
    __shared__ float r1[256], r2[256];
    int t = threadIdx.x;
    r1[t] = sS; r2[t] = sQ;
    __syncthreads();
    for (int o = 128; o > 0; o >>= 1) {
        if (t < o) { r1[t] += r1[t + o]; r2[t] += r2[t + o]; }
        __syncthreads();
    }
    if (t == 0) { g_spqp[lvl * 2] = r1[0]; g_spqp[lvl * 2 + 1] = r2[0]; }
}

// ---- K2: u,v,w vectors per level (reductions over 2C per output d) ----
__global__ void k_uvw(PtrSet ps) {
    int lvl = blockIdx.x;
    int C = c_C[lvl];
    int d = threadIdx.x;   // 512 threads
    const float* __restrict__ W   = ps.W[lvl];
    const float* __restrict__ gg  = ps.lng[lvl];
    const float* __restrict__ bb  = ps.lnb[lvl];
    const float* __restrict__ pm  = g_pm + lvl * 2048;
    float u = 0.f, v = 0.f, w = 0.f;
    int twoC = 2 * C;
    for (int j = 0; j < twoC; ++j) {
        float Wv = W[(size_t)j * ND + d];
        float gv = gg[j];
        v += gv * Wv;
        w += bb[j] * Wv;
        if (j >= C) u += pm[j - C] * gv * Wv;
    }
    w += ps.blin[lvl][d];
    g_u[lvl * ND + d] = u;
    g_v[lvl * ND + d] = v;
    g_w[lvl * ND + d] = w;
}

// ---- K3: Wg = g_top ⊙ W_top, stacked ----
__global__ void k_wg(PtrSet ps) {
    int idx = blockIdx.x * blockDim.x + threadIdx.x;
    if (idx >= 3840 * ND) return;
    int row = idx / ND, d = idx % ND;
    int lvl, j;
    if (row < 256)       { lvl = 0; j = row; }
    else if (row < 768)  { lvl = 1; j = row - 256; }
    else if (row < 1792) { lvl = 2; j = row - 768; }
    else                 { lvl = 3; j = row - 1792; }
    g_Wg[idx] = ps.lng[lvl][j] * ps.W[lvl][(size_t)j * ND + d];
}

// ---- K4: normalized text features with scale folded in ----
__global__ void k_text(PtrSet ps) {
    int k = blockIdx.x, d = threadIdx.x;
    float x = ps.text[k * ND + d];
    __shared__ float red[ND];
    red[d] = x * x;
    __syncthreads();
    for (int o = ND / 2; o > 0; o >>= 1) {
        if (d < o) red[d] += red[d + o];
        __syncthreads();
    }
    float n = fmaxf(sqrtf(red[0]), 1e-12f);
    float sc = fmaxf(ps.scale[0], 1e-4f) * (1.0f / sqrtf((float)ND));
    g_text[k * ND + d] = x / n * sc;
}

// ---- K5: per-row sum/sumsq of pooled (warp per row, float4) ----
__global__ void k_rowstats(PtrSet ps) {
    int gw = (blockIdx.x * blockDim.x + threadIdx.x) >> 5;
    int lane = threadIdx.x & 31;
    int lvl = gw >> 13;            // / NB
    int r = gw & (NB - 1);
    int C = c_C[lvl];
    const float4* __restrict__ row = (const float4*)(ps.pooled[lvl] + (size_t)r * C);
    int n4 = C >> 2;
    float S = 0.f, Q = 0.f;
    for (int j = lane; j < n4; j += 32) {
        float4 v = row[j];
        S += v.x + v.y + v.z + v.w;
        Q += v.x * v.x + v.y * v.y + v.z * v.z + v.w * v.w;
    }
    #pragma unroll
    for (int o = 16; o; o >>= 1) {
        S += __shfl_xor_sync(0xffffffffu, S, o);
        Q += __shfl_xor_sync(0xffffffffu, Q, o);
    }
    if (lane == 0) { g_rs[gw * 2] = S; g_rs[gw * 2 + 1] = Q; }
}

// ---- K6: tiled fp32 GEMM (pooled @ Wg_top) with fused LN/ReLU epilogue ----
__global__ void __launch_bounds__(256) k_gemm(const float* __restrict__ A, int lvl) {
    const int C = c_C[lvl];
    const float* __restrict__ Bm = g_Wg + (size_t)c_wgoff[lvl] * ND;
    __shared__ float As[8][132];   // transposed, padded
    __shared__ float Bs[8][128];
    const int bn = blockIdx.x * 128;
    const int bm = blockIdx.y * 128;
    const int tid = threadIdx.x;
    const int tx = tid & 15, ty = tid >> 4;
    float acc[8][8] = {};

    for (int k0 = 0; k0 < C; k0 += 8) {
        #pragma unroll
        for (int i = 0; i < 4; ++i) {
            int idx = tid + i * 256;
            int r = idx >> 3, c = idx & 7;
            As[c][r] = A[(size_t)(bm + r) * C + (k0 + c)];
        }
        #pragma unroll
        for (int i = 0; i < 4; ++i) {
            int idx = tid + i * 256;
            int r = idx >> 7, c = idx & 127;
            Bs[r][c] = Bm[(size_t)(k0 + r) * ND + (bn + c)];
        }
        __syncthreads();
        #pragma unroll
        for (int k = 0; k < 8; ++k) {
            float a[8], b[8];
            #pragma unroll
            for (int i = 0; i < 8; ++i) a[i] = As[k][ty * 8 + i];
            #pragma unroll
            for (int j = 0; j < 8; ++j) b[j] = Bs[k][tx * 8 + j];
            #pragma unroll
            for (int i = 0; i < 8; ++i)
                #pragma unroll
                for (int j = 0; j < 8; ++j)
                    acc[i][j] = fmaf(a[i], b[j], acc[i][j]);
        }
        __syncthreads();
    }

    // epilogue: h = relu(s*(G+u) - s*m*v + w)
    const float Sp = g_spqp[lvl * 2], Qp = g_spqp[lvl * 2 + 1];
    const float inv2C = 1.0f / (2.0f * (float)C);
    float uu[8], vv[8], ww[8];
    #pragma unroll
    for (int j = 0; j < 8; ++j) {
        int d = bn + tx * 8 + j;
        uu[j] = g_u[lvl * ND + d];
        vv[j] = g_v[lvl * ND + d];
        ww[j] = g_w[lvl * ND + d];
    }
    float* __restrict__ H = g_h + (size_t)lvl * NB * ND;
    #pragma unroll
    for (int i = 0; i < 8; ++i) {
        int m = bm + ty * 8 + i;
        float S = g_rs[((size_t)lvl * NB + m) * 2];
        float Q = g_rs[((size_t)lvl * NB + m) * 2 + 1];
        float mean = (S + Sp) * inv2C;
        float var = (Q + Qp) * inv2C - mean * mean;
        float s = rsqrtf(var + LN_EPS);
        float sm = s * mean;
        #pragma unroll
        for (int j = 0; j < 8; ++j) {
            float hv = s * (acc[i][j] + uu[j]) - sm * vv[j] + ww[j];
            H[(size_t)m * ND + (bn + tx * 8 + j)] = fmaxf(hv, 0.0f);
        }
    }
}

// ---- K7: l2-norm + 8 text dots -> pre-softmax logits into d_out ----
__global__ void __launch_bounds__(256) k_out(float* __restrict__ out) {
    __shared__ float tf[NK * ND];
    for (int i = threadIdx.x; i < NK * ND; i += 256) tf[i] = g_text[i];
    __syncthreads();
    int warp = threadIdx.x >> 5, lane = threadIdx.x & 31;
    int base = blockIdx.x * 64 + warp * 8;
    for (int rr = 0; rr < 8; ++rr) {
        int gr = base + rr;
        int lvl = gr >> 13;
        int b = gr & (NB - 1);
        const float4* __restrict__ hrow = (const float4*)(g_h + (size_t)gr * ND);
        float sq = 0.f;
        float dots[NK];
        #pragma unroll
        for (int k = 0; k < NK; ++k) dots[k] = 0.f;
        #pragma unroll
        for (int q = 0; q < 4; ++q) {
            float4 h4 = hrow[lane + 32 * q];
            sq += h4.x * h4.x + h4.y * h4.y + h4.z * h4.z + h4.w * h4.w;
            #pragma unroll
            for (int k = 0; k < NK; ++k) {
                float4 t4 = ((const float4*)(tf + k * ND))[lane + 32 * q];
                dots[k] += h4.x * t4.x + h4.y * t4.y + h4.z * t4.z + h4.w * t4.w;
            }
        }
        #pragma unroll
        for (int o = 16; o; o >>= 1) {
            sq += __shfl_xor_sync(0xffffffffu, sq, o);
            #pragma unroll
            for (int k = 0; k < NK; ++k)
                dots[k] += __shfl_xor_sync(0xffffffffu, dots[k], o);
        }
        float inv = 1.0f / fmaxf(sqrtf(sq), 1e-12f);
        #pragma unroll
        for (int k = 0; k < NK; ++k)
            if (lane == k)
                out[(size_t)b * (NK * NL) + k * NL + lvl] = dots[k] * inv;
    }
}

// ---- K8: softmax over L=4 (in-place on d_out) ----
__global__ void k_softmax(float* __restrict__ out) {
    int i = blockIdx.x * blockDim.x + threadIdx.x;
    if (i >= NB * NK) return;
    float4 v = ((float4*)out)[i];
    float mx = fmaxf(fmaxf(v.x, v.y), fmaxf(v.z, v.w));
    float ex = expf(v.x - mx), ey = expf(v.y - mx);
    float ez = expf(v.z - mx), ew = expf(v.w - mx);
    float s = 1.0f / (ex + ey + ez + ew);
    v.x = ex * s; v.y = ey * s; v.z = ez * s; v.w = ew * s;
    ((float4*)out)[i] = v;
}

extern "C" void kernel_launch(void* const* d_in, const int* in_sizes, int n_in,
                              void* d_out, int out_size) {
    PtrSet ps;
    // Disambiguate metadata ordering via in_sizes[1]:
    //   interleaved (setup_inputs insertion order): d_in[1] = proto_0 (64*256 = 16384)
    //   grouped (signature order):                  d_in[1] = pooled_1 (8192*512)
    bool interleaved = (in_sizes[1] == NP * 256);
    if (interleaved) {
        for (int i = 0; i < NL; ++i) {
            ps.pooled[i] = (const float*)d_in[6 * i + 0];
            ps.proto[i]  = (const float*)d_in[6 * i + 1];
            ps.lng[i]    = (const float*)d_in[6 * i + 2];
            ps.lnb[i]    = (const float*)d_in[6 * i + 3];
            ps.W[i]      = (const float*)d_in[6 * i + 4];
            ps.blin[i]   = (const float*)d_in[6 * i + 5];
        }
    } else {
        for (int i = 0; i < NL; ++i) {
            ps.pooled[i] = (const float*)d_in[0 + i];
            ps.proto[i]  = (const float*)d_in[4 + i];
            ps.lng[i]    = (const float*)d_in[8 + i];
            ps.lnb[i]    = (const float*)d_in[12 + i];
            ps.W[i]      = (const float*)d_in[16 + i];
            ps.blin[i]   = (const float*)d_in[20 + i];
        }
    }
    ps.text  = (const float*)d_in[24];
    ps.scale = (const float*)d_in[25];
    float* out = (float*)d_out;

    k_protomean<<<NL, 256>>>(ps);
    k_uvw<<<NL, ND>>>(ps);
    k_wg<<<(3840 * ND + 255) / 256, 256>>>(ps);
    k_text<<<NK, ND>>>(ps);
    k_rowstats<<<NL * NB / 8, 256>>>(ps);
    for (int lvl = 0; lvl < NL; ++lvl) {
        k_gemm<<<dim3(ND / 128, NB / 128), 256>>>(ps.pooled[lvl], lvl);
    }
    k_out<<<NL * NB / 64, 256>>>(out);
    k_softmax<<<(NB * NK) / 256, 256>>>(out);
}

// round 4
// speedup vs baseline: 6.3100x; 6.3100x over previous
#include <cuda_runtime.h>
#include <cuda_bf16.h>
#include <cstdint>
#include <math.h>

#define NB 8192
#define NP 64
#define NK 8
#define ND 512
#define NL 4
#define LN_EPS 1e-5f

__constant__ int c_C[NL]     = {256, 512, 1024, 2048};
__constant__ int c_off[NL]   = {0, 256, 768, 1792};   // row offsets (cumulative C)

// ---- scratch (static device globals) ----
__device__ float g_pm[NL * 2048];              // proto column means
__device__ float g_spqp[NL * 2];               // sum/sumsq of proto-mean half
__device__ float g_u[NL * ND];
__device__ float g_v[NL * ND];
__device__ float g_w[NL * ND];
__device__ float g_up[NL * 16 * ND];           // deterministic partials
__device__ float g_vp[NL * 16 * ND];
__device__ float g_wp[NL * 16 * ND];
__device__ float g_text[NK * ND];              // l2norm * clip(scale)/sqrt(D)
__device__ __nv_bfloat16 g_Wgb[3840 * ND];     // g_top ⊙ W_top (bf16, stacked)
__device__ __nv_bfloat16 g_Abf[(size_t)NB * 3840];  // pooled in bf16, stacked
__device__ float g_rs[NL * NB * 2];            // per-row (S,Q) of pooled

struct PtrSet {
    const float* pooled[NL];
    const float* proto[NL];
    const float* lng[NL];
    const float* lnb[NL];
    const float* W[NL];
    const float* blin[NL];
    const float* text;
    const float* scale;
};

// ---- K1: proto column means + sum/sumsq ----
__global__ void k_protomean(PtrSet ps) {
    int lvl = blockIdx.x;
    int C = c_C[lvl];
    const float* __restrict__ proto = ps.proto[lvl];
    float* pm = g_pm + lvl * 2048;
    float sS = 0.f, sQ = 0.f;
    for (int j = threadIdx.x; j < C; j += blockDim.x) {
        float s = 0.f;
        #pragma unroll 8
        for (int p = 0; p < NP; ++p) s += proto[p * C + j];
        float m = s * (1.0f / NP);
        pm[j] = m; sS += m; sQ += m * m;
    }
    __shared__ float r1[256], r2[256];
    int t = threadIdx.x;
    r1[t] = sS; r2[t] = sQ;
    __syncthreads();
    for (int o = 128; o > 0; o >>= 1) {
        if (t < o) { r1[t] += r1[t + o]; r2[t] += r2[t + o]; }
        __syncthreads();
    }
    if (t == 0) { g_spqp[lvl * 2] = r1[0]; g_spqp[lvl * 2 + 1] = r2[0]; }
}

// ---- K2: u,v,w partials (64 blocks, deterministic) ----
__global__ void k_uvw(PtrSet ps) {
    int lvl = blockIdx.y;
    int bx = blockIdx.x;                 // 0..15
    int C = c_C[lvl];
    int seg = (2 * C) / 16;
    int j0 = bx * seg;
    int d = threadIdx.x;                 // 512
    const float* __restrict__ W  = ps.W[lvl];
    const float* __restrict__ gg = ps.lng[lvl];
    const float* __restrict__ bb = ps.lnb[lvl];
    const float* __restrict__ pm = g_pm + lvl * 2048;
    float u = 0.f, v = 0.f, w = 0.f;
    for (int j = j0; j < j0 + seg; ++j) {
        float Wv = W[(size_t)j * ND + d];
        float gv = gg[j];
        v += gv * Wv;
        w += bb[j] * Wv;
        if (j >= C) u += pm[j - C] * gv * Wv;
    }
    int o = (lvl * 16 + bx) * ND + d;
    g_up[o] = u; g_vp[o] = v; g_wp[o] = w;
}

// ---- K2b: reduce partials + add linear bias into w ----
__global__ void k_uvw_fin(PtrSet ps) {
    int lvl = blockIdx.x, d = threadIdx.x;
    float u = 0.f, v = 0.f, w = 0.f;
    #pragma unroll
    for (int p = 0; p < 16; ++p) {
        int o = (lvl * 16 + p) * ND + d;
        u += g_up[o]; v += g_vp[o]; w += g_wp[o];
    }
    g_u[lvl * ND + d] = u;
    g_v[lvl * ND + d] = v;
    g_w[lvl * ND + d] = w + ps.blin[lvl][d];
}

// ---- K3: Wg = g_top ⊙ W_top (bf16) ----
__global__ void k_wg(PtrSet ps) {
    int idx = blockIdx.x * blockDim.x + threadIdx.x;
    if (idx >= 3840 * ND) return;
    int row = idx / ND, d = idx % ND;
    int lvl, j;
    if (row < 256)       { lvl = 0; j = row; }
    else if (row < 768)  { lvl = 1; j = row - 256; }
    else if (row < 1792) { lvl = 2; j = row - 768; }
    else                 { lvl = 3; j = row - 1792; }
    g_Wgb[idx] = __float2bfloat16(ps.lng[lvl][j] * ps.W[lvl][(size_t)j * ND + d]);
}

// ---- K4: normalized text features, scale folded ----
__global__ void k_text(PtrSet ps) {
    int k = blockIdx.x, d = threadIdx.x;
    float x = ps.text[k * ND + d];
    __shared__ float red[ND];
    red[d] = x * x;
    __syncthreads();
    for (int o = ND / 2; o > 0; o >>= 1) {
        if (d < o) red[d] += red[d + o];
        __syncthreads();
    }
    float n = fmaxf(sqrtf(red[0]), 1e-12f);
    float sc = fmaxf(ps.scale[0], 1e-4f) * (1.0f / sqrtf((float)ND));
    g_text[k * ND + d] = x / n * sc;
}

// ---- K5: per-row sum/sumsq of pooled + bf16 conversion ----
__global__ void k_rowstats(PtrSet ps) {
    int gw = (blockIdx.x * blockDim.x + threadIdx.x) >> 5;
    int lane = threadIdx.x & 31;
    int lvl = gw >> 13;
    int r = gw & (NB - 1);
    int C = c_C[lvl];
    const float4* __restrict__ row = (const float4*)(ps.pooled[lvl] + (size_t)r * C);
    __nv_bfloat162* __restrict__ arow =
        (__nv_bfloat162*)(g_Abf + (size_t)NB * c_off[lvl] + (size_t)r * C);
    int n4 = C >> 2;
    float S = 0.f, Q = 0.f;
    for (int j = lane; j < n4; j += 32) {
        float4 v = row[j];
        S += v.x + v.y + v.z + v.w;
        Q += v.x * v.x + v.y * v.y + v.z * v.z + v.w * v.w;
        arow[j * 2]     = __floats2bfloat162_rn(v.x, v.y);
        arow[j * 2 + 1] = __floats2bfloat162_rn(v.z, v.w);
    }
    #pragma unroll
    for (int o = 16; o; o >>= 1) {
        S += __shfl_xor_sync(0xffffffffu, S, o);
        Q += __shfl_xor_sync(0xffffffffu, Q, o);
    }
    if (lane == 0) { g_rs[gw * 2] = S; g_rs[gw * 2 + 1] = Q; }
}

// ================= fused GEMM (bf16 mma.sync) + LN/ReLU + l2norm + dots ======
// BM=64, BN=512(full), BK=32. 512 threads = 16 warps (2 x 8). Warp tile 32x64.
// smem byte layout (dynamic):
//   [0)      Bs: 2 stages x 32 x 520 bf16 = 66560   (reused as h-tile 64x520 bf16)
//   [66560)  As: 2 stages x 64 x 40  bf16 = 10240
//   [76800)  text: 8 x 512 f32             = 16384
//   [93184)  u,v,w: 3 x 512 f32            = 6144
#define SM_AS   66560
#define SM_TEXT 76800
#define SM_UVW  93184
#define SM_TOT  99328
#define ASTRIDE 40
#define BSTRIDE 520

__device__ __forceinline__ void cp16(uint32_t dst, const void* src) {
    asm volatile("cp.async.cg.shared.global [%0], [%1], 16;\n" :: "r"(dst), "l"(src));
}

__global__ void __launch_bounds__(512, 1) k_fused(float* __restrict__ out) {
    extern __shared__ char smem[];
    const int lvl = blockIdx.y;
    const int C = c_C[lvl];
    const int bm = blockIdx.x * 64;
    const int tid = threadIdx.x;
    const int wid = tid >> 5, lane = tid & 31;
    const int wm = wid >> 3, wn = wid & 7;

    const __nv_bfloat16* __restrict__ Ag = g_Abf + (size_t)NB * c_off[lvl] + (size_t)bm * C;
    const __nv_bfloat16* __restrict__ Bg = g_Wgb + (size_t)c_off[lvl] * ND;

    __nv_bfloat16* Bs = (__nv_bfloat16*)smem;
    __nv_bfloat16* As = (__nv_bfloat16*)(smem + SM_AS);
    float* text_s = (float*)(smem + SM_TEXT);
    float* uvw_s  = (float*)(smem + SM_UVW);     // u[512], v[512], w[512]
    __nv_bfloat16* h_s = (__nv_bfloat16*)smem;   // reuse Bs after k-loop

    const uint32_t Bs_u = (uint32_t)__cvta_generic_to_shared(Bs);
    const uint32_t As_u = (uint32_t)__cvta_generic_to_shared(As);

    // stage epilogue constants into smem
    for (int i = tid; i < NK * ND; i += 512) text_s[i] = g_text[i];
    if (tid < ND) {
        uvw_s[tid]            = g_u[lvl * ND + tid];
        uvw_s[ND + tid]       = g_v[lvl * ND + tid];
        uvw_s[2 * ND + tid]   = g_w[lvl * ND + tid];
    }

    float acc[2][8][4];
    #pragma unroll
    for (int i = 0; i < 2; ++i)
        #pragma unroll
        for (int j = 0; j < 8; ++j)
            #pragma unroll
            for (int r = 0; r < 4; ++r) acc[i][j][r] = 0.f;

    const int niter = C >> 5;

    // stage loader: As 64x32 (256 chunks of 16B), Bs 32x512 (2048 chunks)
    auto load_stage = [&](int it) {
        int buf = it & 1;
        int k0 = it << 5;
        if (tid < 256) {
            int r = tid >> 2, c = tid & 3;
            cp16(As_u + (buf * 64 * ASTRIDE + r * ASTRIDE + c * 8) * 2,
                 Ag + (size_t)r * C + k0 + c * 8);
        }
        #pragma unroll
        for (int q = 0; q < 4; ++q) {
            int idx = tid + q * 512;
            int r = idx >> 6, c = idx & 63;
            cp16(Bs_u + (buf * 32 * BSTRIDE + r * BSTRIDE + c * 8) * 2,
                 Bg + (size_t)(k0 + r) * ND + c * 8);
        }
        asm volatile("cp.async.commit_group;\n" ::: "memory");
    };

    load_stage(0);

    for (int it = 0; it < niter; ++it) {
        asm volatile("cp.async.wait_group 0;\n" ::: "memory");
        __syncthreads();
        if (it + 1 < niter) load_stage(it + 1);

        const int buf = it & 1;
        const uint32_t Ab = As_u + buf * 64 * ASTRIDE * 2;
        const uint32_t Bb = Bs_u + buf * 32 * BSTRIDE * 2;

        #pragma unroll
        for (int ks = 0; ks < 32; ks += 16) {
            uint32_t afrag[2][4];
            #pragma unroll
            for (int mf = 0; mf < 2; ++mf) {
                uint32_t addr = Ab + ((wm * 32 + mf * 16 + (lane & 15)) * ASTRIDE
                                      + ks + (lane >> 4) * 8) * 2;
                asm volatile("ldmatrix.sync.aligned.m8n8.x4.shared.b16 {%0,%1,%2,%3}, [%4];\n"
                             : "=r"(afrag[mf][0]), "=r"(afrag[mf][1]),
                               "=r"(afrag[mf][2]), "=r"(afrag[mf][3])
                             : "r"(addr));
            }
            uint32_t bfrag[8][2];
            #pragma unroll
            for (int p = 0; p < 4; ++p) {
                uint32_t addr = Bb + ((ks + (lane & 15)) * BSTRIDE
                                      + wn * 64 + p * 16 + (lane >> 4) * 8) * 2;
                asm volatile("ldmatrix.sync.aligned.m8n8.x4.trans.shared.b16 {%0,%1,%2,%3}, [%4];\n"
                             : "=r"(bfrag[2 * p][0]), "=r"(bfrag[2 * p][1]),
                               "=r"(bfrag[2 * p + 1][0]), "=r"(bfrag[2 * p + 1][1])
                             : "r"(addr));
            }
            #pragma unroll
            for (int mf = 0; mf < 2; ++mf)
                #pragma unroll
                for (int nf = 0; nf < 8; ++nf)
                    asm volatile(
                        "mma.sync.aligned.m16n8k16.row.col.f32.bf16.bf16.f32 "
                        "{%0,%1,%2,%3}, {%4,%5,%6,%7}, {%8,%9}, {%0,%1,%2,%3};\n"
                        : "+f"(acc[mf][nf][0]), "+f"(acc[mf][nf][1]),
                          "+f"(acc[mf][nf][2]), "+f"(acc[mf][nf][3])
                        : "r"(afrag[mf][0]), "r"(afrag[mf][1]),
                          "r"(afrag[mf][2]), "r"(afrag[mf][3]),
                          "r"(bfrag[nf][0]), "r"(bfrag[nf][1]));
        }
        __syncthreads();
    }

    // ---- epilogue: LN + ReLU -> h (bf16) into smem ----
    const float Sp = g_spqp[lvl * 2], Qp = g_spqp[lvl * 2 + 1];
    const float inv2C = 1.0f / (2.0f * (float)C);
    const int qr = lane >> 2, qc = (lane & 3) * 2;

    #pragma unroll
    for (int mf = 0; mf < 2; ++mf) {
        int rA = wm * 32 + mf * 16 + qr;     // local rows rA, rA+8
        float2 sq0 = ((const float2*)g_rs)[lvl * NB + bm + rA];
        float2 sq1 = ((const float2*)g_rs)[lvl * NB + bm + rA + 8];
        float mean0 = (sq0.x + Sp) * inv2C;
        float var0  = (sq0.y + Qp) * inv2C - mean0 * mean0;
        float s0 = rsqrtf(var0 + LN_EPS), sm0 = s0 * mean0;
        float mean1 = (sq1.x + Sp) * inv2C;
        float var1  = (sq1.y + Qp) * inv2C - mean1 * mean1;
        float s1 = rsqrtf(var1 + LN_EPS), sm1 = s1 * mean1;
        #pragma unroll
        for (int nf = 0; nf < 8; ++nf) {
            #pragma unroll
            for (int r = 0; r < 4; ++r) {
                int col = wn * 64 + nf * 8 + qc + (r & 1);
                int row = rA + 8 * (r >> 1);
                float s  = (r < 2) ? s0  : s1;
                float sm = (r < 2) ? sm0 : sm1;
                float hv = s * (acc[mf][nf][r] + uvw_s[col]) - sm * uvw_s[ND + col]
                           + uvw_s[2 * ND + col];
                h_s[row * BSTRIDE + col] = __float2bfloat16(fmaxf(hv, 0.f));
            }
        }
    }
    __syncthreads();

    // ---- l2norm + 8 text dots ----
    #pragma unroll
    for (int i = 0; i < 4; ++i) {
        int r = wid * 4 + i;
        float sq = 0.f;
        float dk[NK];
        #pragma unroll
        for (int k = 0; k < NK; ++k) dk[k] = 0.f;
        #pragma unroll
        for (int q = 0; q < 16; ++q) {
            int c = lane + 32 * q;
            float hv = __bfloat162float(h_s[r * BSTRIDE + c]);
            sq += hv * hv;
            #pragma unroll
            for (int k = 0; k < NK; ++k) dk[k] += hv * text_s[k * ND + c];
        }
        #pragma unroll
        for (int o = 16; o; o >>= 1) {
            sq += __shfl_xor_sync(0xffffffffu, sq, o);
            #pragma unroll
            for (int k = 0; k < NK; ++k)
                dk[k] += __shfl_xor_sync(0xffffffffu, dk[k], o);
        }
        float inv = 1.0f / fmaxf(sqrtf(sq), 1e-12f);
        if (lane < NK)
            out[(size_t)(bm + r) * (NK * NL) + lane * NL + lvl] = dk[lane] * inv;
    }
}

// ---- softmax over L=4 ----
__global__ void k_softmax(float* __restrict__ out) {
    int i = blockIdx.x * blockDim.x + threadIdx.x;
    if (i >= NB * NK) return;
    float4 v = ((float4*)out)[i];
    float mx = fmaxf(fmaxf(v.x, v.y), fmaxf(v.z, v.w));
    float ex = expf(v.x - mx), ey = expf(v.y - mx);
    float ez = expf(v.z - mx), ew = expf(v.w - mx);
    float s = 1.0f / (ex + ey + ez + ew);
    v.x = ex * s; v.y = ey * s; v.z = ez * s; v.w = ew * s;
    ((float4*)out)[i] = v;
}

extern "C" void kernel_launch(void* const* d_in, const int* in_sizes, int n_in,
                              void* d_out, int out_size) {
    PtrSet ps;
    bool interleaved = (in_sizes[1] == NP * 256);
    if (interleaved) {
        for (int i = 0; i < NL; ++i) {
            ps.pooled[i] = (const float*)d_in[6 * i + 0];
            ps.proto[i]  = (const float*)d_in[6 * i + 1];
            ps.lng[i]    = (const float*)d_in[6 * i + 2];
            ps.lnb[i]    = (const float*)d_in[6 * i + 3];
            ps.W[i]      = (const float*)d_in[6 * i + 4];
            ps.blin[i]   = (const float*)d_in[6 * i + 5];
        }
    } else {
        for (int i = 0; i < NL; ++i) {
            ps.pooled[i] = (const float*)d_in[0 + i];
            ps.proto[i]  = (const float*)d_in[4 + i];
            ps.lng[i]    = (const float*)d_in[8 + i];
            ps.lnb[i]    = (const float*)d_in[12 + i];
            ps.W[i]      = (const float*)d_in[16 + i];
            ps.blin[i]   = (const float*)d_in[20 + i];
        }
    }
    ps.text  = (const float*)d_in[24];
    ps.scale = (const float*)d_in[25];
    float* out = (float*)d_out;

    static bool attr_done = false;
    if (!attr_done) {
        cudaFuncSetAttribute(k_fused, cudaFuncAttributeMaxDynamicSharedMemorySize, SM_TOT);
        attr_done = true;
    }

    k_protomean<<<NL, 256>>>(ps);
    k_uvw<<<dim3(16, NL), ND>>>(ps);
    k_uvw_fin<<<NL, ND>>>(ps);
    k_wg<<<(3840 * ND + 255) / 256, 256>>>(ps);
    k_text<<<NK, ND>>>(ps);
    k_rowstats<<<NL * NB / 8, 256>>>(ps);
    k_fused<<<dim3(NB / 64, NL), 512, SM_TOT>>>(out);
    k_softmax<<<(NB * NK) / 256, 256>>>(out);
}

// round 6
// speedup vs baseline: 7.0797x; 1.1220x over previous
#include <cuda_runtime.h>
#include <cuda_bf16.h>
#include <cstdint>
#include <math.h>

#define NB 8192
#define NP 64
#define NK 8
#define ND 512
#define NL 4
#define LN_EPS 1e-5f

__constant__ int c_C[NL]     = {256, 512, 1024, 2048};
__constant__ int c_off[NL]   = {0, 256, 768, 1792};   // row offsets (cumulative C)

// ---- scratch (static device globals) ----
__device__ float g_pm[NL * 2048];              // proto column means
__device__ float g_spp[NL * 8 * 2];            // partial sum/sumsq of proto-mean half
__device__ float g_spqp[NL * 2];               // combined
__device__ float g_u[NL * ND];
__device__ float g_v[NL * ND];
__device__ float g_w[NL * ND];
__device__ float g_up[NL * 16 * ND];           // deterministic partials
__device__ float g_vp[NL * 16 * ND];
__device__ float g_wp[NL * 16 * ND];
__device__ float g_text[NK * ND];              // l2norm * clip(scale)/sqrt(D)
__device__ __nv_bfloat16 g_Wgb[3840 * ND];     // g_top ⊙ W_top (bf16, stacked)
__device__ __nv_bfloat16 g_Abf[(size_t)NB * 3840];  // pooled in bf16, stacked
__device__ float g_rs[NL * NB * 2];            // per-row (S,Q) of pooled
__device__ float g_part[(size_t)NL * 2 * NB * 9];   // per (lvl,half,row): 8 dots + sq

struct PtrSet {
    const float* pooled[NL];
    const float* proto[NL];
    const float* lng[NL];
    const float* lnb[NL];
    const float* W[NL];
    const float* blin[NL];
    const float* text;
    const float* scale;
};

// ---- K1: proto column means + partial sum/sumsq (8 col-chunks x NL blocks) ----
__global__ void k_protomean(PtrSet ps) {
    int lvl = blockIdx.y;
    int bx = blockIdx.x;                 // 0..7
    int C = c_C[lvl];
    int seg = C / 8;
    int j0 = bx * seg;
    const float* __restrict__ proto = ps.proto[lvl];
    float* pm = g_pm + lvl * 2048;
    float sS = 0.f, sQ = 0.f;
    for (int j = j0 + threadIdx.x; j < j0 + seg; j += blockDim.x) {
        float s = 0.f;
        #pragma unroll 8
        for (int p = 0; p < NP; ++p) s += proto[p * C + j];
        float m = s * (1.0f / NP);
        pm[j] = m; sS += m; sQ += m * m;
    }
    __shared__ float r1[256], r2[256];
    int t = threadIdx.x;
    r1[t] = sS; r2[t] = sQ;
    __syncthreads();
    for (int o = 128; o > 0; o >>= 1) {
        if (t < o) { r1[t] += r1[t + o]; r2[t] += r2[t + o]; }
        __syncthreads();
    }
    if (t == 0) {
        g_spp[(lvl * 8 + bx) * 2]     = r1[0];
        g_spp[(lvl * 8 + bx) * 2 + 1] = r2[0];
    }
}

// ---- K2: u,v,w partials (64 blocks, deterministic) ----
__global__ void k_uvw(PtrSet ps) {
    int lvl = blockIdx.y;
    int bx = blockIdx.x;                 // 0..15
    int C = c_C[lvl];
    int seg = (2 * C) / 16;
    int j0 = bx * seg;
    int d = threadIdx.x;                 // 512
    const float* __restrict__ W  = ps.W[lvl];
    const float* __restrict__ gg = ps.lng[lvl];
    const float* __restrict__ bb = ps.lnb[lvl];
    const float* __restrict__ pm = g_pm + lvl * 2048;
    float u = 0.f, v = 0.f, w = 0.f;
    for (int j = j0; j < j0 + seg; ++j) {
        float Wv = W[(size_t)j * ND + d];
        float gv = gg[j];
        v += gv * Wv;
        w += bb[j] * Wv;
        if (j >= C) u += pm[j - C] * gv * Wv;
    }
    int o = (lvl * 16 + bx) * ND + d;
    g_up[o] = u; g_vp[o] = v; g_wp[o] = w;
}

// ---- K2b: reduce partials + add linear bias into w + combine spqp ----
__global__ void k_uvw_fin(PtrSet ps) {
    int lvl = blockIdx.x, d = threadIdx.x;
    float u = 0.f, v = 0.f, w = 0.f;
    #pragma unroll
    for (int p = 0; p < 16; ++p) {
        int o = (lvl * 16 + p) * ND + d;
        u += g_up[o]; v += g_vp[o]; w += g_wp[o];
    }
    g_u[lvl * ND + d] = u;
    g_v[lvl * ND + d] = v;
    g_w[lvl * ND + d] = w + ps.blin[lvl][d];
    if (d == 0) {
        float s = 0.f, q = 0.f;
        #pragma unroll
        for (int p = 0; p < 8; ++p) {
            s += g_spp[(lvl * 8 + p) * 2];
            q += g_spp[(lvl * 8 + p) * 2 + 1];
        }
        g_spqp[lvl * 2] = s; g_spqp[lvl * 2 + 1] = q;
    }
}

// ---- K3: Wg = g_top ⊙ W_top (bf16) ----
__global__ void k_wg(PtrSet ps) {
    int idx = blockIdx.x * blockDim.x + threadIdx.x;
    if (idx >= 3840 * ND) return;
    int row = idx / ND, d = idx % ND;
    int lvl, j;
    if (row < 256)       { lvl = 0; j = row; }
    else if (row < 768)  { lvl = 1; j = row - 256; }
    else if (row < 1792) { lvl = 2; j = row - 768; }
    else                 { lvl = 3; j = row - 1792; }
    g_Wgb[idx] = __float2bfloat16(ps.lng[lvl][j] * ps.W[lvl][(size_t)j * ND + d]);
}

// ---- K4: normalized text features, scale folded ----
__global__ void k_text(PtrSet ps) {
    int k = blockIdx.x, d = threadIdx.x;
    float x = ps.text[k * ND + d];
    __shared__ float red[ND];
    red[d] = x * x;
    __syncthreads();
    for (int o = ND / 2; o > 0; o >>= 1) {
        if (d < o) red[d] += red[d + o];
        __syncthreads();
    }
    float n = fmaxf(sqrtf(red[0]), 1e-12f);
    float sc = fmaxf(ps.scale[0], 1e-4f) * (1.0f / sqrtf((float)ND));
    g_text[k * ND + d] = x / n * sc;
}

// ---- K5: per-row sum/sumsq of pooled + bf16 conversion ----
__global__ void k_rowstats(PtrSet ps) {
    int gw = (blockIdx.x * blockDim.x + threadIdx.x) >> 5;
    int lane = threadIdx.x & 31;
    int lvl = gw >> 13;
    int r = gw & (NB - 1);
    int C = c_C[lvl];
    const float4* __restrict__ row = (const float4*)(ps.pooled[lvl] + (size_t)r * C);
    __nv_bfloat162* __restrict__ arow =
        (__nv_bfloat162*)(g_Abf + (size_t)NB * c_off[lvl] + (size_t)r * C);
    int n4 = C >> 2;
    float S = 0.f, Q = 0.f;
    for (int j = lane; j < n4; j += 32) {
        float4 v = row[j];
        S += v.x + v.y + v.z + v.w;
        Q += v.x * v.x + v.y * v.y + v.z * v.z + v.w * v.w;
        arow[j * 2]     = __floats2bfloat162_rn(v.x, v.y);
        arow[j * 2 + 1] = __floats2bfloat162_rn(v.z, v.w);
    }
    #pragma unroll
    for (int o = 16; o; o >>= 1) {
        S += __shfl_xor_sync(0xffffffffu, S, o);
        Q += __shfl_xor_sync(0xffffffffu, Q, o);
    }
    if (lane == 0) { g_rs[gw * 2] = S; g_rs[gw * 2 + 1] = Q; }
}

// ===== fused GEMM (bf16 mma.sync) + LN/ReLU + partial l2norm/dots ============
// BM=128, BN=256 (half of D), BK=32. 512 threads = 16 warps (wm=wid>>2, wn=wid&3).
// 3-stage cp.async pipeline. Each block writes 9 partials per row to g_part.
// smem layout (bytes):
//   [0)      Bs: 3 x 32 x 264 bf16 = 50688   (reused as red[4][128][9] f32 after)
//   [50688)  As: 3 x 128 x 40 bf16 = 30720
//   [81408)  text: 8 x 256 f32     = 8192
//   [89600)  uvw:  3 x 256 f32     = 3072
#define SM_AS   50688
#define SM_TEXT 81408
#define SM_UVW  89600
#define SM_TOT  92672
#define ASTRIDE 40
#define BSTRIDE 264
#define BNH 256

__device__ __forceinline__ void cp16(uint32_t dst, const void* src) {
    asm volatile("cp.async.cg.shared.global [%0], [%1], 16;\n" :: "r"(dst), "l"(src));
}

__global__ void __launch_bounds__(512, 1) k_fused() {
    extern __shared__ char smem[];
    const int lvl = blockIdx.z;
    const int half = blockIdx.y;
    const int C = c_C[lvl];
    const int bm = blockIdx.x * 128;
    const int tid = threadIdx.x;
    const int wid = tid >> 5, lane = tid & 31;
    const int wm = wid >> 2, wn = wid & 3;

    const __nv_bfloat16* __restrict__ Ag = g_Abf + (size_t)NB * c_off[lvl] + (size_t)bm * C;
    const __nv_bfloat16* __restrict__ Bg = g_Wgb + (size_t)c_off[lvl] * ND + half * BNH;

    float* text_s = (float*)(smem + SM_TEXT);
    float* uvw_s  = (float*)(smem + SM_UVW);
    float* red_s  = (float*)smem;                // overlay on Bs after k-loop

    const uint32_t Bs_u = (uint32_t)__cvta_generic_to_shared(smem);
    const uint32_t As_u = (uint32_t)__cvta_generic_to_shared(smem + SM_AS);

    // stage epilogue constants (local column slice)
    for (int i = tid; i < NK * BNH; i += 512) {
        int k = i >> 8, c = i & (BNH - 1);
        text_s[i] = g_text[k * ND + half * BNH + c];
    }
    if (tid < BNH) {
        uvw_s[tid]           = g_u[lvl * ND + half * BNH + tid];
        uvw_s[BNH + tid]     = g_v[lvl * ND + half * BNH + tid];
        uvw_s[2 * BNH + tid] = g_w[lvl * ND + half * BNH + tid];
    }

    float acc[2][8][4];
    #pragma unroll
    for (int i = 0; i < 2; ++i)
        #pragma unroll
        for (int j = 0; j < 8; ++j)
            #pragma unroll
            for (int r = 0; r < 4; ++r) acc[i][j][r] = 0.f;

    const int niter = C >> 5;

    // stage loader: As 128x32 (512 chunks), Bs 32x256 (1024 chunks)
    auto load_stage = [&](int it) {
        int buf = it - (it / 3) * 3;
        int k0 = it << 5;
        {
            int r = tid >> 2, c = tid & 3;
            cp16(As_u + (buf * 128 * ASTRIDE + r * ASTRIDE + c * 8) * 2,
                 Ag + (size_t)r * C + k0 + c * 8);
        }
        #pragma unroll
        for (int q = 0; q < 2; ++q) {
            int idx = tid + q * 512;
            int r = idx >> 5, c = idx & 31;
            cp16(Bs_u + (buf * 32 * BSTRIDE + r * BSTRIDE + c * 8) * 2,
                 Bg + (size_t)(k0 + r) * ND + c * 8);
        }
        asm volatile("cp.async.commit_group;\n" ::: "memory");
    };

    load_stage(0);
    if (niter > 1) load_stage(1);

    for (int it = 0; it < niter; ++it) {
        if (it + 1 < niter)
            asm volatile("cp.async.wait_group 1;\n" ::: "memory");
        else
            asm volatile("cp.async.wait_group 0;\n" ::: "memory");
        __syncthreads();
        if (it + 2 < niter) load_stage(it + 2);

        const int buf = it - (it / 3) * 3;
        const uint32_t Ab = As_u + buf * 128 * ASTRIDE * 2;
        const uint32_t Bb = Bs_u + buf * 32 * BSTRIDE * 2;

        #pragma unroll
        for (int ks = 0; ks < 32; ks += 16) {
            uint32_t afrag[2][4];
            #pragma unroll
            for (int mf = 0; mf < 2; ++mf) {
                uint32_t addr = Ab + ((wm * 32 + mf * 16 + (lane & 15)) * ASTRIDE
                                      + ks + (lane >> 4) * 8) * 2;
                asm volatile("ldmatrix.sync.aligned.m8n8.x4.shared.b16 {%0,%1,%2,%3}, [%4];\n"
                             : "=r"(afrag[mf][0]), "=r"(afrag[mf][1]),
                               "=r"(afrag[mf][2]), "=r"(afrag[mf][3])
                             : "r"(addr));
            }
            uint32_t bfrag[8][2];
            #pragma unroll
            for (int p = 0; p < 4; ++p) {
                uint32_t addr = Bb + ((ks + (lane & 15)) * BSTRIDE
                                      + wn * 64 + p * 16 + (lane >> 4) * 8) * 2;
                asm volatile("ldmatrix.sync.aligned.m8n8.x4.trans.shared.b16 {%0,%1,%2,%3}, [%4];\n"
                             : "=r"(bfrag[2 * p][0]), "=r"(bfrag[2 * p][1]),
                               "=r"(bfrag[2 * p + 1][0]), "=r"(bfrag[2 * p + 1][1])
                             : "r"(addr));
            }
            #pragma unroll
            for (int mf = 0; mf < 2; ++mf)
                #pragma unroll
                for (int nf = 0; nf < 8; ++nf)
                    asm volatile(
                        "mma.sync.aligned.m16n8k16.row.col.f32.bf16.bf16.f32 "
                        "{%0,%1,%2,%3}, {%4,%5,%6,%7}, {%8,%9}, {%0,%1,%2,%3};\n"
                        : "+f"(acc[mf][nf][0]), "+f"(acc[mf][nf][1]),
                          "+f"(acc[mf][nf][2]), "+f"(acc[mf][nf][3])
                        : "r"(afrag[mf][0]), "r"(afrag[mf][1]),
                          "r"(afrag[mf][2]), "r"(afrag[mf][3]),
                          "r"(bfrag[nf][0]), "r"(bfrag[nf][1]));
        }
        __syncthreads();
    }

    // all compute done; Bs region now reusable as reduction buffer
    // (the __syncthreads at the end of the last iteration guarantees this)

    // ---- epilogue: LN + ReLU, accumulate sq + 8 text dots per row ----
    const float Sp = g_spqp[lvl * 2], Qp = g_spqp[lvl * 2 + 1];
    const float inv2C = 1.0f / (2.0f * (float)C);
    const int qr = lane >> 2, qc = (lane & 3) * 2;

    #pragma unroll
    for (int mf = 0; mf < 2; ++mf) {
        int R0 = wm * 32 + mf * 16 + qr;     // local rows R0, R0+8
        float2 sqr0 = ((const float2*)g_rs)[lvl * NB + bm + R0];
        float2 sqr1 = ((const float2*)g_rs)[lvl * NB + bm + R0 + 8];
        float mean0 = (sqr0.x + Sp) * inv2C;
        float var0  = (sqr0.y + Qp) * inv2C - mean0 * mean0;
        float s0 = rsqrtf(var0 + LN_EPS), sm0 = s0 * mean0;
        float mean1 = (sqr1.x + Sp) * inv2C;
        float var1  = (sqr1.y + Qp) * inv2C - mean1 * mean1;
        float s1 = rsqrtf(var1 + LN_EPS), sm1 = s1 * mean1;

        float sq0 = 0.f, sq1 = 0.f;
        float d0[NK], d1[NK];
        #pragma unroll
        for (int k = 0; k < NK; ++k) { d0[k] = 0.f; d1[k] = 0.f; }

        #pragma unroll
        for (int nf = 0; nf < 8; ++nf) {
            #pragma unroll
            for (int r = 0; r < 4; ++r) {
                int col = wn * 64 + nf * 8 + qc + (r & 1);
                float s  = (r < 2) ? s0  : s1;
                float sm = (r < 2) ? sm0 : sm1;
                float hv = s * (acc[mf][nf][r] + uvw_s[col]) - sm * uvw_s[BNH + col]
                           + uvw_s[2 * BNH + col];
                hv = fmaxf(hv, 0.f);
                if (r < 2) {
                    sq0 += hv * hv;
                    #pragma unroll
                    for (int k = 0; k < NK; ++k) d0[k] += hv * text_s[k * BNH + col];
                } else {
                    sq1 += hv * hv;
                    #pragma unroll
                    for (int k = 0; k < NK; ++k) d1[k] += hv * text_s[k * BNH + col];
                }
            }
        }
        // reduce across the 4 lanes sharing each row (lane&3 varies)
        #pragma unroll
        for (int o = 1; o <= 2; o <<= 1) {
            sq0 += __shfl_xor_sync(0xffffffffu, sq0, o);
            sq1 += __shfl_xor_sync(0xffffffffu, sq1, o);
            #pragma unroll
            for (int k = 0; k < NK; ++k) {
                d0[k] += __shfl_xor_sync(0xffffffffu, d0[k], o);
                d1[k] += __shfl_xor_sync(0xffffffffu, d1[k], o);
            }
        }
        if ((lane & 3) == 0) {
            #pragma unroll
            for (int k = 0; k < NK; ++k) {
                red_s[(wn * 128 + R0) * 9 + k]     = d0[k];
                red_s[(wn * 128 + R0 + 8) * 9 + k] = d1[k];
            }
            red_s[(wn * 128 + R0) * 9 + 8]     = sq0;
            red_s[(wn * 128 + R0 + 8) * 9 + 8] = sq1;
        }
    }
    __syncthreads();

    // combine over the 4 wn warps, write partials to global
    for (int idx = tid; idx < 128 * 9; idx += 512) {
        int row = idx / 9, kk = idx - row * 9;
        float s = red_s[(0 * 128 + row) * 9 + kk] + red_s[(1 * 128 + row) * 9 + kk]
                + red_s[(2 * 128 + row) * 9 + kk] + red_s[(3 * 128 + row) * 9 + kk];
        g_part[((size_t)(lvl * 2 + half) * NB + bm + row) * 9 + kk] = s;
    }
}

// ---- final: combine halves, normalize, softmax over L=4 ----
__global__ void k_final(float* __restrict__ out) {
    int id = blockIdx.x * blockDim.x + threadIdx.x;   // (b, k)
    if (id >= NB * NK) return;
    int b = id >> 3, k = id & 7;
    float lg[NL];
    #pragma unroll
    for (int lvl = 0; lvl < NL; ++lvl) {
        const float* p0 = &g_part[((size_t)(lvl * 2 + 0) * NB + b) * 9];
        const float* p1 = &g_part[((size_t)(lvl * 2 + 1) * NB + b) * 9];
        float dq = p0[k] + p1[k];
        float sq = p0[8] + p1[8];
        lg[lvl] = dq / fmaxf(sqrtf(sq), 1e-12f);
    }
    float mx = fmaxf(fmaxf(lg[0], lg[1]), fmaxf(lg[2], lg[3]));
    float e0 = expf(lg[0] - mx), e1 = expf(lg[1] - mx);
    float e2 = expf(lg[2] - mx), e3 = expf(lg[3] - mx);
    float inv = 1.0f / (e0 + e1 + e2 + e3);
    float4 o = make_float4(e0 * inv, e1 * inv, e2 * inv, e3 * inv);
    ((float4*)out)[(size_t)b * NK + k] = o;
}

extern "C" void kernel_launch(void* const* d_in, const int* in_sizes, int n_in,
                              void* d_out, int out_size) {
    PtrSet ps;
    bool interleaved = (in_sizes[1] == NP * 256);
    if (interleaved) {
        for (int i = 0; i < NL; ++i) {
            ps.pooled[i] = (const float*)d_in[6 * i + 0];
            ps.proto[i]  = (const float*)d_in[6 * i + 1];
            ps.lng[i]    = (const float*)d_in[6 * i + 2];
            ps.lnb[i]    = (const float*)d_in[6 * i + 3];
            ps.W[i]      = (const float*)d_in[6 * i + 4];
            ps.blin[i]   = (const float*)d_in[6 * i + 5];
        }
    } else {
        for (int i = 0; i < NL; ++i) {
            ps.pooled[i] = (const float*)d_in[0 + i];
            ps.proto[i]  = (const float*)d_in[4 + i];
            ps.lng[i]    = (const float*)d_in[8 + i];
            ps.lnb[i]    = (const float*)d_in[12 + i];
            ps.W[i]      = (const float*)d_in[16 + i];
            ps.blin[i]   = (const float*)d_in[20 + i];
        }
    }
    ps.text  = (const float*)d_in[24];
    ps.scale = (const float*)d_in[25];
    float* out = (float*)d_out;

    static bool attr_done = false;
    if (!attr_done) {
        cudaFuncSetAttribute(k_fused, cudaFuncAttributeMaxDynamicSharedMemorySize, SM_TOT);
        attr_done = true;
    }

    k_protomean<<<dim3(8, NL), 256>>>(ps);
    k_uvw<<<dim3(16, NL), ND>>>(ps);
    k_uvw_fin<<<NL, ND>>>(ps);
    k_wg<<<(3840 * ND + 255) / 256, 256>>>(ps);
    k_text<<<NK, ND>>>(ps);
    k_rowstats<<<NL * NB / 8, 256>>>(ps);
    k_fused<<<dim3(NB / 128, 2, NL), 512, SM_TOT>>>();
    k_final<<<(NB * NK + 255) / 256, 256>>>(out);
}